// round 14
// baseline (speedup 1.0000x reference)
#include <cuda_runtime.h>
#include <cuda_fp16.h>
#include <cstdint>

// ============================================================================
// Problem sizes (fixed for this dataset)
// ============================================================================
static constexpr int DIMN  = 4096;
static constexpr int HID   = 11008;
static constexpr int MROWS = 8192;   // B*S = 4*2048

static constexpr int BM = 128, BK = 64, BN_EACH = 64;
static constexpr int MT      = MROWS / BM;        // 64 m-groups
static constexpr int NT1_N   = HID / BN_EACH;     // 172 n-tiles (GEMM1)
static constexpr int NT2_N   = DIMN / 128;        // 32 n-tiles (GEMM2, 2x64)
static constexpr int NT1     = MT * NT1_N;        // 11008
static constexpr int NT2     = MT * NT2_N;        // 2048
static constexpr int NT      = NT1 + NT2;         // 13056
static constexpr int KCH1    = DIMN / BK;         // 64
static constexpr int KCH2    = HID / BK;          // 172

// ============================================================================
// Device scratch + sync state (allocation-free rule: __device__ globals)
// ============================================================================
static __device__ __align__(256) __half g_x  [(size_t)MROWS * DIMN];
static __device__ __align__(256) __half g_wg [(size_t)HID   * DIMN];
static __device__ __align__(256) __half g_wu [(size_t)HID   * DIMN];
static __device__ __align__(256) __half g_wd [(size_t)DIMN  * HID ];
static __device__ __align__(256) __half g_mid[(size_t)MROWS * HID ];
static __device__ int g_cnt[MT];     // per-m-group GEMM1 tile completion count
static __device__ int g_wd_done;     // cvt_wd block completion count

// ============================================================================
// PTX helpers — compute_103-safe only (cp.async, ldmatrix, mma.sync.m16n8k16)
// ============================================================================
__device__ __forceinline__ uint32_t smem_to_u32(const void* smem_ptr) {
    uint32_t addr;
    asm("{ .reg .u64 tmp; cvta.to.shared.u64 tmp, %1; cvt.u32.u64 %0, tmp; }"
        : "=r"(addr) : "l"(smem_ptr));
    return addr;
}

__device__ __forceinline__ void cp_async16(uint32_t dst, const void* src) {
    asm volatile("cp.async.cg.shared.global [%0], [%1], 16;\n"
                 :: "r"(dst), "l"(src) : "memory");
}
#define CP_COMMIT() asm volatile("cp.async.commit_group;\n" ::: "memory")
template <int N>
__device__ __forceinline__ void cp_wait() {
    asm volatile("cp.async.wait_group %0;\n" :: "n"(N) : "memory");
}

__device__ __forceinline__ void ldsm_x4(uint32_t& r0, uint32_t& r1,
                                        uint32_t& r2, uint32_t& r3, uint32_t addr) {
    asm volatile("ldmatrix.sync.aligned.m8n8.x4.shared.b16 {%0,%1,%2,%3}, [%4];"
                 : "=r"(r0), "=r"(r1), "=r"(r2), "=r"(r3) : "r"(addr));
}

__device__ __forceinline__ void mma16816(float* c, const uint32_t* a, const uint32_t* b) {
    asm volatile(
        "mma.sync.aligned.m16n8k16.row.col.f32.f16.f16.f32 "
        "{%0,%1,%2,%3}, {%4,%5,%6,%7}, {%8,%9}, {%0,%1,%2,%3};"
        : "+f"(c[0]), "+f"(c[1]), "+f"(c[2]), "+f"(c[3])
        : "r"(a[0]), "r"(a[1]), "r"(a[2]), "r"(a[3]), "r"(b[0]), "r"(b[1]));
}

// ============================================================================
// Converts. cvt_xw blocks GEMM1; cvt_wd runs forked, completion signaled
// device-side via g_wd_done (so the fused kernel's phase 2 is race-free).
// ============================================================================
static constexpr int N8X = (MROWS * DIMN) / 8;
static constexpr int N8W = (HID * DIMN) / 8;
static constexpr int BX  = N8X / 256;            // 16384
static constexpr int BW  = N8W / 256;            // 22016

__device__ __forceinline__ uint4 cvt_i32x8(const int4* src, int i) {
    int4 a = src[2 * i];
    int4 c = src[2 * i + 1];
    __half2 h0 = __halves2half2(__int2half_rn(a.x), __int2half_rn(a.y));
    __half2 h1 = __halves2half2(__int2half_rn(a.z), __int2half_rn(a.w));
    __half2 h2 = __halves2half2(__int2half_rn(c.x), __int2half_rn(c.y));
    __half2 h3 = __halves2half2(__int2half_rn(c.z), __int2half_rn(c.w));
    uint4 r;
    r.x = *reinterpret_cast<uint32_t*>(&h0);
    r.y = *reinterpret_cast<uint32_t*>(&h1);
    r.z = *reinterpret_cast<uint32_t*>(&h2);
    r.w = *reinterpret_cast<uint32_t*>(&h3);
    return r;
}

__global__ void __launch_bounds__(256) cvt_xw(
    const float4* __restrict__ x, const int4* __restrict__ wg,
    const int4* __restrict__ wu,
    uint4* __restrict__ ox, uint4* __restrict__ owg, uint4* __restrict__ owu)
{
    int b = blockIdx.x;
    if (b < BX) {
        int i = b * 256 + threadIdx.x;
        float4 a = x[2 * i];
        float4 c = x[2 * i + 1];
        __half2 h0 = __floats2half2_rn(a.x, a.y);
        __half2 h1 = __floats2half2_rn(a.z, a.w);
        __half2 h2 = __floats2half2_rn(c.x, c.y);
        __half2 h3 = __floats2half2_rn(c.z, c.w);
        uint4 r;
        r.x = *reinterpret_cast<uint32_t*>(&h0);
        r.y = *reinterpret_cast<uint32_t*>(&h1);
        r.z = *reinterpret_cast<uint32_t*>(&h2);
        r.w = *reinterpret_cast<uint32_t*>(&h3);
        ox[i] = r;
        return;
    }
    b -= BX;
    if (b < BW) { owg[b * 256 + threadIdx.x] = cvt_i32x8(wg, b * 256 + threadIdx.x); }
    else        { b -= BW; owu[b * 256 + threadIdx.x] = cvt_i32x8(wu, b * 256 + threadIdx.x); }
}

__global__ void __launch_bounds__(256) cvt_wd(const int4* __restrict__ wd,
                                              uint4* __restrict__ owd)
{
    int i = blockIdx.x * 256 + threadIdx.x;
    owd[i] = cvt_i32x8(wd, i);
    __threadfence();
    __syncthreads();
    if (threadIdx.x == 0) atomicAdd(&g_wd_done, 1);
}

// ============================================================================
// FUSED persistent GEMM kernel. Every tile runs the SAME mainloop shape
// (NB=2, BN_EACH=64, BM=128, BK=64; 8 warps 2m x 4n; occ 2; 3-stage pipe).
//   Phase 1 (t <  NT1): A=x, B0=wg, B1=wu tiles; SwiGLU epilogue -> g_mid;
//                       signals g_cnt[mt] (threadfence + atomicAdd).
//   Phase 2 (t >= NT1): A=g_mid, B0/B1 = two 64-col halves of a 128-col wd
//                       tile; scale epilogue -> d_out (fp32). Spins on
//                       g_cnt[mt]==172 and g_wd_done==BW before loading.
// Per-element FP summation order identical to the split kernels.
// Never-draining prefetch within phase 1; pipeline drains at phase-2 tile
// boundaries (restart cost ~1.5us, overlapped at occ 2).
// ============================================================================
__global__ void __launch_bounds__(256, 2) ffn_fused(
    const __half* __restrict__ X,
    const __half* __restrict__ WG,
    const __half* __restrict__ WU,
    const __half* __restrict__ WD,
    __half* __restrict__ MIDP,
    float* __restrict__ OUT,
    const float* __restrict__ sgp,
    const float* __restrict__ sup,
    const float* __restrict__ sdp)
{
    constexpr int NTHR = 256;
    constexpr int WN_COLS = BN_EACH / 4;           // 16
    constexpr int MI   = 4;
    constexpr int NMMA = WN_COLS / 8;              // 2
    constexpr int NJ   = 2 * (NMMA / 2);           // 2
    constexpr int A_BYTES = BM * BK * 2;           // 16384
    constexpr int B_BYTES = BN_EACH * BK * 2;      // 8192
    constexpr int STAGE_BYTES = A_BYTES + 2 * B_BYTES;   // 32768
    constexpr int A_ITERS = (BM * 8) / NTHR;       // 4
    constexpr int B_ITERS = (BN_EACH * 8) / NTHR;  // 2
    constexpr int GM = 8;

    extern __shared__ char smem[];
    const uint32_t sb = smem_to_u32(smem);

    const int tid  = threadIdx.x;
    const int wid  = tid >> 5;
    const int lane = tid & 31;
    const int wm   = wid & 1;
    const int wn   = wid >> 1;
    const int quad = lane >> 3;
    const int qr   = lane & 7;
    const int G    = gridDim.x;

    // ---- hoisted LDSM address components (row&7 == qr for all fragments) ---
    const uint32_t xr   = (uint32_t)(qr << 4);
    const uint32_t xr60 = xr & 0x60;
    const uint32_t xr10 = xr & 0x10;
    uint32_t kxo[4];
#pragma unroll
    for (int ks = 0; ks < 4; ks++) kxo[ks] = ((uint32_t)(ks * 32)) ^ xr60;

    uint32_t baseA[MI];
#pragma unroll
    for (int mi = 0; mi < MI; mi++) {
        int row = wm * 64 + mi * 16 + (quad & 1) * 8 + qr;
        baseA[mi] = (uint32_t)(row * 128) + (((uint32_t)((quad >> 1) * 16)) ^ xr10);
    }
    uint32_t baseB[NJ];
#pragma unroll
    for (int g = 0; g < 2; g++) {
        int row = wn * WN_COLS + (quad >> 1) * 8 + qr;
        baseB[g] = (uint32_t)(A_BYTES + g * B_BYTES + row * 128) +
                   (((uint32_t)((quad & 1) * 16)) ^ xr10);
    }

    // ---- loader thread constants ----
    const int lrow = tid >> 3;                    // 0..31
    const int lch  = tid & 7;
    const uint32_t ldst = lrow * 128 + ((lch * 16) ^ ((lrow & 7) << 4));

    // per-tile state (pointers already offset by lrow/lch for the loader)
    const __half* aP;
    const __half* bP0;
    const __half* bP1;
    size_t rstep;

    auto set_tile = [&](int t, int& mt, int& nt, bool& is2, int& kch) {
        is2 = (t >= NT1);
        if (!is2) {
            const int tpg = GM * NT1_N;
            mt = (t / tpg) * GM + (t % tpg) % GM;
            nt = (t % tpg) / GM;
            kch = KCH1;
            rstep = (size_t)32 * DIMN;
            aP  = X  + (size_t)(mt * BM + lrow) * DIMN + lch * 8;
            bP0 = WG + (size_t)(nt * BN_EACH + lrow) * DIMN + lch * 8;
            bP1 = WU + (size_t)(nt * BN_EACH + lrow) * DIMN + lch * 8;
        } else {
            const int t2 = t - NT1;
            const int tpg = GM * NT2_N;
            mt = (t2 / tpg) * GM + (t2 % tpg) % GM;
            nt = (t2 % tpg) / GM;
            kch = KCH2;
            rstep = (size_t)32 * HID;
            aP  = MIDP + (size_t)(mt * BM + lrow) * HID + lch * 8;
            bP0 = WD + (size_t)(nt * 128 + lrow) * HID + lch * 8;
            bP1 = WD + (size_t)(nt * 128 + 64 + lrow) * HID + lch * 8;
        }
    };

    auto load_stage = [&](int kc, int slot) {
        const uint32_t st = sb + slot * STAGE_BYTES + ldst;
        const int k0 = kc * BK;
#pragma unroll
        for (int it = 0; it < A_ITERS; it++)
            cp_async16(st + it * 4096, aP + k0 + it * rstep);
        const uint32_t bbase = st + A_BYTES;
#pragma unroll
        for (int it = 0; it < B_ITERS; it++)
            cp_async16(bbase + it * 4096, bP0 + k0 + it * rstep);
#pragma unroll
        for (int it = 0; it < B_ITERS; it++)
            cp_async16(bbase + B_BYTES + it * 4096, bP1 + k0 + it * rstep);
    };

    auto load_part = [&](int kc, int slot, int p) {
        const uint32_t st = sb + slot * STAGE_BYTES + ldst;
        const int k0 = kc * BK;
        cp_async16(st + p * 4096, aP + k0 + p * rstep);
        const __half* bp = (p >> 1) ? bP1 : bP0;
        const int it = p & 1;
        cp_async16(st + A_BYTES + (p >> 1) * B_BYTES + it * 4096,
                   bp + k0 + it * rstep);
    };

    const float sg = *sgp;
    const float su = *sup;
    const float sd = *sdp;

    float acc[2][MI][NMMA][4];
    bool primed = false;
    int cslot = 0;

    for (int t = blockIdx.x; t < NT; t += G) {
        int mt, nt, kch;
        bool is2;
        set_tile(t, mt, nt, is2, kch);

        // phase-2 dependency wait (before any loads of this tile)
        if (is2) {
            if (tid == 0) {
                while (*(volatile int*)&g_wd_done < BW) {}
                while (*(volatile int*)&g_cnt[mt] < NT1_N) {}
                __threadfence();
            }
            __syncthreads();
        }

#pragma unroll
        for (int g = 0; g < 2; g++)
#pragma unroll
            for (int mi = 0; mi < MI; mi++)
#pragma unroll
                for (int ni = 0; ni < NMMA; ni++)
#pragma unroll
                    for (int q = 0; q < 4; q++) acc[g][mi][ni][q] = 0.f;

        // prime pipeline if drained (first tile / after phase transition)
        if (!primed) {
            __syncthreads();   // prior tile's readers done with all slots
            load_stage(0, cslot); CP_COMMIT();
            load_stage(1, (cslot + 1 == 3) ? 0 : cslot + 1); CP_COMMIT();
            primed = true;
        }

        // prefetch next tile only within phase 1 (same K/rstep guaranteed)
        const bool prenext = (t + G) < NT1;

        for (int kc = 0; kc < kch; kc++) {
            cp_wait<1>();
            __syncthreads();

            if (kc == kch - 2 && prenext) {
                int xm, xn, xk;
                bool xi;
                set_tile(t + G, xm, xn, xi, xk);   // phase-1 only: K unchanged
            }
            const bool do_pre = (kc < kch - 2) || prenext;
            const int preK = (kc + 2 < kch) ? (kc + 2) : (kc + 2 - kch);
            const int pslot = (cslot + 2 >= 3) ? (cslot - 1) : (cslot + 2);

            const uint32_t st = sb + cslot * STAGE_BYTES;
#pragma unroll
            for (int ks = 0; ks < 4; ks++) {
                const uint32_t stk = st + kxo[ks];
                uint32_t fa[MI][4];
#pragma unroll
                for (int mi = 0; mi < MI; mi++)
                    ldsm_x4(fa[mi][0], fa[mi][1], fa[mi][2], fa[mi][3],
                            stk + baseA[mi]);
                uint32_t fb[NJ][4];
#pragma unroll
                for (int jj = 0; jj < NJ; jj++)
                    ldsm_x4(fb[jj][0], fb[jj][1], fb[jj][2], fb[jj][3],
                            stk + baseB[jj]);
                if (do_pre) load_part(preK, pslot, ks);
#pragma unroll
                for (int g = 0; g < 2; g++)
#pragma unroll
                    for (int mi = 0; mi < MI; mi++)
#pragma unroll
                        for (int ni = 0; ni < NMMA; ni++)
                            mma16816(acc[g][mi][ni], fa[mi],
                                     &fb[g][(ni & 1) * 2]);
            }
            CP_COMMIT();
            cslot = (cslot + 1 == 3) ? 0 : cslot + 1;
        }
        primed = prenext;    // pipeline holds next tile's chunks 0,1 iff prefetched

        // ---- epilogue ----
        if (!is2) {
#pragma unroll
            for (int mi = 0; mi < MI; mi++)
#pragma unroll
                for (int ni = 0; ni < NMMA; ni++) {
                    int row0 = mt * BM + wm * 64 + mi * 16 + (lane >> 2);
                    int col  = nt * BN_EACH + wn * WN_COLS + ni * 8 + (lane & 3) * 2;
#pragma unroll
                    for (int h = 0; h < 2; h++) {
                        int row = row0 + h * 8;
                        float g0 = sg * acc[0][mi][ni][2 * h + 0];
                        float g1 = sg * acc[0][mi][ni][2 * h + 1];
                        float u0 = su * acc[1][mi][ni][2 * h + 0];
                        float u1 = su * acc[1][mi][ni][2 * h + 1];
                        float r0 = g0 / (1.f + __expf(-g0)) * u0;
                        float r1 = g1 / (1.f + __expf(-g1)) * u1;
                        *(__half2*)(MIDP + (size_t)row * HID + col) =
                            __floats2half2_rn(r0, r1);
                    }
                }
            __threadfence();
            __syncthreads();
            if (tid == 0) atomicAdd(&g_cnt[mt], 1);
        } else {
#pragma unroll
            for (int g = 0; g < 2; g++)
#pragma unroll
                for (int mi = 0; mi < MI; mi++)
#pragma unroll
                    for (int ni = 0; ni < NMMA; ni++) {
                        int row0 = mt * BM + wm * 64 + mi * 16 + (lane >> 2);
                        int col  = nt * 128 + g * 64 + wn * WN_COLS + ni * 8 +
                                   (lane & 3) * 2;
#pragma unroll
                        for (int h = 0; h < 2; h++) {
                            int row = row0 + h * 8;
                            float2 v;
                            v.x = sd * acc[g][mi][ni][2 * h + 0];
                            v.y = sd * acc[g][mi][ni][2 * h + 1];
                            *(float2*)(OUT + (size_t)row * DIMN + col) = v;
                        }
                    }
        }
    }
}

// ============================================================================
// Host side — fork cvt_wd; fused kernel consumes its completion device-side.
// ============================================================================
extern "C" void kernel_launch(void* const* d_in, const int* in_sizes, int n_in,
                              void* d_out, int out_size) {
    const float* x  = (const float*)d_in[0];
    const int*   wg = (const int*)d_in[1];
    const int*   wu = (const int*)d_in[2];
    const int*   wd = (const int*)d_in[3];
    const float* sg = (const float*)d_in[4];
    const float* su = (const float*)d_in[5];
    const float* sd = (const float*)d_in[6];

    void *px, *pwg, *pwu, *pwd, *pmid, *pcnt, *pwdf;
    cudaGetSymbolAddress(&px,  g_x);
    cudaGetSymbolAddress(&pwg, g_wg);
    cudaGetSymbolAddress(&pwu, g_wu);
    cudaGetSymbolAddress(&pwd, g_wd);
    cudaGetSymbolAddress(&pmid, g_mid);
    cudaGetSymbolAddress(&pcnt, g_cnt);
    cudaGetSymbolAddress(&pwdf, g_wd_done);

    int dev = 0, sms = 148;
    cudaGetDevice(&dev);
    cudaDeviceGetAttribute(&sms, cudaDevAttrMultiProcessorCount, dev);
    int grid = 2 * sms;
    if (grid > NT) grid = NT;

    constexpr int SMEM_BYTES = 3 * 32768;   // 98304 per CTA -> 2 CTAs/SM
    cudaFuncSetAttribute(ffn_fused,
                         cudaFuncAttributeMaxDynamicSharedMemorySize, SMEM_BYTES);

    // zero sync state (graph-capturable memset nodes; re-zeroed every replay)
    cudaMemsetAsync(pcnt, 0, sizeof(int) * MT, 0);
    cudaMemsetAsync(pwdf, 0, sizeof(int), 0);

    // fork stream + events (host objects; O(1) calls total)
    cudaStream_t s1;
    cudaEvent_t eFork, eJoin;
    cudaStreamCreateWithFlags(&s1, cudaStreamNonBlocking);
    cudaEventCreateWithFlags(&eFork, cudaEventDisableTiming);
    cudaEventCreateWithFlags(&eJoin, cudaEventDisableTiming);

    cudaEventRecord(eFork, 0);
    cudaStreamWaitEvent(s1, eFork, 0);

    // forked branch: down-proj convert (phase 2 gates on g_wd_done anyway)
    cvt_wd<<<BW, 256, 0, s1>>>((const int4*)wd, (uint4*)pwd);
    cudaEventRecord(eJoin, s1);

    // main branch: x + gate/up converts, then the fused persistent kernel
    cvt_xw<<<BX + 2 * BW, 256>>>(
        (const float4*)x, (const int4*)wg, (const int4*)wu,
        (uint4*)px, (uint4*)pwg, (uint4*)pwu);

    ffn_fused<<<grid, 256, SMEM_BYTES>>>(
        (const __half*)px, (const __half*)pwg, (const __half*)pwu,
        (const __half*)pwd, (__half*)pmid, (float*)d_out, sg, su, sd);

    // join forked branch into the captured stream
    cudaStreamWaitEvent(0, eJoin, 0);
}

// round 15
// speedup vs baseline: 1.0265x; 1.0265x over previous
#include <cuda_runtime.h>
#include <cuda_fp16.h>
#include <cstdint>

// ============================================================================
// Problem sizes (fixed for this dataset)
// ============================================================================
static constexpr int DIMN  = 4096;
static constexpr int HID   = 11008;
static constexpr int MROWS = 8192;   // B*S = 4*2048

// ============================================================================
// Device scratch (allocation-free rule: __device__ globals)
// ============================================================================
static __device__ __align__(256) __half g_x  [(size_t)MROWS * DIMN];
static __device__ __align__(256) __half g_wg [(size_t)HID   * DIMN];
static __device__ __align__(256) __half g_wu [(size_t)HID   * DIMN];
static __device__ __align__(256) __half g_wd [(size_t)DIMN  * HID ];
static __device__ __align__(256) __half g_mid[(size_t)MROWS * HID ];

// ============================================================================
// PTX helpers — compute_103-safe only (cp.async, ldmatrix, mma.sync.m16n8k16)
// ============================================================================
__device__ __forceinline__ uint32_t smem_to_u32(const void* smem_ptr) {
    uint32_t addr;
    asm("{ .reg .u64 tmp; cvta.to.shared.u64 tmp, %1; cvt.u32.u64 %0, tmp; }"
        : "=r"(addr) : "l"(smem_ptr));
    return addr;
}

__device__ __forceinline__ void cp_async16(uint32_t dst, const void* src) {
    asm volatile("cp.async.cg.shared.global [%0], [%1], 16;\n"
                 :: "r"(dst), "l"(src) : "memory");
}
#define CP_COMMIT() asm volatile("cp.async.commit_group;\n" ::: "memory")
template <int N>
__device__ __forceinline__ void cp_wait() {
    asm volatile("cp.async.wait_group %0;\n" :: "n"(N) : "memory");
}

__device__ __forceinline__ void ldsm_x4(uint32_t& r0, uint32_t& r1,
                                        uint32_t& r2, uint32_t& r3, uint32_t addr) {
    asm volatile("ldmatrix.sync.aligned.m8n8.x4.shared.b16 {%0,%1,%2,%3}, [%4];"
                 : "=r"(r0), "=r"(r1), "=r"(r2), "=r"(r3) : "r"(addr));
}

__device__ __forceinline__ void mma16816(float* c, const uint32_t* a, const uint32_t* b) {
    asm volatile(
        "mma.sync.aligned.m16n8k16.row.col.f32.f16.f16.f32 "
        "{%0,%1,%2,%3}, {%4,%5,%6,%7}, {%8,%9}, {%0,%1,%2,%3};"
        : "+f"(c[0]), "+f"(c[1]), "+f"(c[2]), "+f"(c[3])
        : "r"(a[0]), "r"(a[1]), "r"(a[2]), "r"(a[3]), "r"(b[0]), "r"(b[1]));
}

// ============================================================================
// Converts, split: cvt_xw (x + gate/up, blocks GEMM1) and cvt_wd (down-proj,
// runs on a forked stream overlapped with GEMM1).
// ============================================================================
static constexpr int N8X = (MROWS * DIMN) / 8;   // 4,194,304 -> 16384 blocks
static constexpr int N8W = (HID * DIMN) / 8;     // 5,636,096 -> 22016 blocks
static constexpr int BX  = N8X / 256;            // 16384
static constexpr int BW  = N8W / 256;            // 22016

__device__ __forceinline__ uint4 cvt_i32x8(const int4* src, int i) {
    int4 a = src[2 * i];
    int4 c = src[2 * i + 1];
    __half2 h0 = __halves2half2(__int2half_rn(a.x), __int2half_rn(a.y));
    __half2 h1 = __halves2half2(__int2half_rn(a.z), __int2half_rn(a.w));
    __half2 h2 = __halves2half2(__int2half_rn(c.x), __int2half_rn(c.y));
    __half2 h3 = __halves2half2(__int2half_rn(c.z), __int2half_rn(c.w));
    uint4 r;
    r.x = *reinterpret_cast<uint32_t*>(&h0);
    r.y = *reinterpret_cast<uint32_t*>(&h1);
    r.z = *reinterpret_cast<uint32_t*>(&h2);
    r.w = *reinterpret_cast<uint32_t*>(&h3);
    return r;
}

__global__ void __launch_bounds__(256) cvt_xw(
    const float4* __restrict__ x, const int4* __restrict__ wg,
    const int4* __restrict__ wu,
    uint4* __restrict__ ox, uint4* __restrict__ owg, uint4* __restrict__ owu)
{
    int b = blockIdx.x;
    if (b < BX) {
        int i = b * 256 + threadIdx.x;
        float4 a = x[2 * i];
        float4 c = x[2 * i + 1];
        __half2 h0 = __floats2half2_rn(a.x, a.y);
        __half2 h1 = __floats2half2_rn(a.z, a.w);
        __half2 h2 = __floats2half2_rn(c.x, c.y);
        __half2 h3 = __floats2half2_rn(c.z, c.w);
        uint4 r;
        r.x = *reinterpret_cast<uint32_t*>(&h0);
        r.y = *reinterpret_cast<uint32_t*>(&h1);
        r.z = *reinterpret_cast<uint32_t*>(&h2);
        r.w = *reinterpret_cast<uint32_t*>(&h3);
        ox[i] = r;
        return;
    }
    b -= BX;
    if (b < BW) { owg[b * 256 + threadIdx.x] = cvt_i32x8(wg, b * 256 + threadIdx.x); }
    else        { b -= BW; owu[b * 256 + threadIdx.x] = cvt_i32x8(wu, b * 256 + threadIdx.x); }
}

__global__ void __launch_bounds__(256) cvt_wd(const int4* __restrict__ wd,
                                              uint4* __restrict__ owd)
{
    int i = blockIdx.x * 256 + threadIdx.x;
    owd[i] = cvt_i32x8(wd, i);
}

// ============================================================================
// PERSISTENT multistage cp.async + mma.sync GEMM (C = A * B^T).
//   NB==2 (BN_EACH=64):  gate+up share A tile; fused SwiGLU -> fp16 mid.
//   NB==1 (BN_EACH=128): down proj; scaled fp32 out.
// CTA tile 128 x 128-total x 64k; 8 warps 2m x 4n; occupancy 2 (3 stages x
// 32KB smem). Never-draining pipeline across tiles (epilogue overlaps next
// tile's prologue loads). R13 champion, byte-identical.
// ============================================================================
template <int NB, int BN_EACH>
__global__ void __launch_bounds__(256, 2) ffn_gemm(
    const __half* __restrict__ A,
    const __half* __restrict__ B0,
    const __half* __restrict__ B1,
    void* __restrict__ outp,
    const float* __restrict__ s0p,
    const float* __restrict__ s1p,
    int K, int ntiles, int ntotal, int ncols)
{
    constexpr int BM = 128, BK = 64;
    constexpr int NTHR = 256;
    constexpr int WN_COLS = BN_EACH / 4;
    constexpr int MI   = 4;
    constexpr int NMMA = WN_COLS / 8;
    constexpr int NJ   = NB * (NMMA / 2);
    constexpr int A_BYTES = BM * BK * 2;
    constexpr int B_BYTES = BN_EACH * BK * 2;
    constexpr int STAGE_BYTES = A_BYTES + NB * B_BYTES;   // 32768
    constexpr int A_ITERS = (BM * 8) / NTHR;
    constexpr int B_ITERS = (BN_EACH * 8) / NTHR;
    constexpr int GM = 8;

    extern __shared__ char smem[];
    const uint32_t sb = smem_to_u32(smem);

    const int tid  = threadIdx.x;
    const int wid  = tid >> 5;
    const int lane = tid & 31;
    const int wm   = wid & 1;
    const int wn   = wid >> 1;
    const int quad = lane >> 3;
    const int qr   = lane & 7;

    const int kch = K / BK;
    const int G   = gridDim.x;

    // ---- hoisted LDSM address components (row&7 == qr for all fragments) ---
    const uint32_t xr   = (uint32_t)(qr << 4);
    const uint32_t xr60 = xr & 0x60;
    const uint32_t xr10 = xr & 0x10;
    uint32_t kxo[4];
#pragma unroll
    for (int ks = 0; ks < 4; ks++) kxo[ks] = ((uint32_t)(ks * 32)) ^ xr60;

    uint32_t baseA[MI];
#pragma unroll
    for (int mi = 0; mi < MI; mi++) {
        int row = wm * 64 + mi * 16 + (quad & 1) * 8 + qr;
        baseA[mi] = (uint32_t)(row * 128) + (((uint32_t)((quad >> 1) * 16)) ^ xr10);
    }
    uint32_t baseB[NJ];
#pragma unroll
    for (int g = 0; g < NB; g++)
#pragma unroll
        for (int j = 0; j < NMMA / 2; j++) {
            int row = wn * WN_COLS + j * 16 + (quad >> 1) * 8 + qr;
            baseB[g * (NMMA / 2) + j] =
                (uint32_t)(A_BYTES + g * B_BYTES + row * 128) +
                (((uint32_t)((quad & 1) * 16)) ^ xr10);
        }

    // ---- loader thread constants ----
    const int lrow = tid >> 3;                    // 0..31
    const int lch  = tid & 7;
    const uint32_t ldst = lrow * 128 + ((lch * 16) ^ ((lrow & 7) << 4));
    const size_t rstep = (size_t)32 * K;

    auto decode = [&](int t, int& mt, int& nt) {
        const int tpg = GM * ntiles;
        mt = (t / tpg) * GM + (t % tpg) % GM;
        nt = (t % tpg) / GM;
    };

    const __half* aP;
    const __half* bP0;
    const __half* bP1;
    auto set_ptrs = [&](int t) {
        int mt, nt;
        decode(t, mt, nt);
        aP  = A  + (size_t)(mt * BM + lrow) * K + lch * 8;
        bP0 = B0 + (size_t)(nt * BN_EACH + lrow) * K + lch * 8;
        bP1 = B1 + (size_t)(nt * BN_EACH + lrow) * K + lch * 8;
    };

    auto load_stage = [&](int kc, int slot) {
        const uint32_t st = sb + slot * STAGE_BYTES + ldst;
        const int k0 = kc * BK;
#pragma unroll
        for (int it = 0; it < A_ITERS; it++)
            cp_async16(st + it * 4096, aP + k0 + it * rstep);
        const uint32_t bbase = st + A_BYTES;
#pragma unroll
        for (int it = 0; it < B_ITERS; it++)
            cp_async16(bbase + it * 4096, bP0 + k0 + it * rstep);
        if (NB == 2) {
#pragma unroll
            for (int it = 0; it < B_ITERS; it++)
                cp_async16(bbase + B_BYTES + it * 4096, bP1 + k0 + it * rstep);
        }
    };

    auto load_part = [&](int kc, int slot, int p) {
        const uint32_t st = sb + slot * STAGE_BYTES + ldst;
        const int k0 = kc * BK;
        cp_async16(st + p * 4096, aP + k0 + p * rstep);
        if (NB == 2) {
            const __half* bp = (p >> 1) ? bP1 : bP0;
            const int it = p & 1;
            cp_async16(st + A_BYTES + (p >> 1) * B_BYTES + it * 4096,
                       bp + k0 + it * rstep);
        } else {
            cp_async16(st + A_BYTES + p * 4096, bP0 + k0 + p * rstep);
        }
    };

    float acc[NB][MI][NMMA][4];
#pragma unroll
    for (int g = 0; g < NB; g++)
#pragma unroll
        for (int mi = 0; mi < MI; mi++)
#pragma unroll
            for (int ni = 0; ni < NMMA; ni++)
#pragma unroll
                for (int q = 0; q < 4; q++) acc[g][mi][ni][q] = 0.f;

    int t = blockIdx.x;
    if (t >= ntotal) return;
    set_ptrs(t);

    load_stage(0, 0); CP_COMMIT();
    load_stage(1, 1); CP_COMMIT();
    int cslot = 0;

    const float s0 = *s0p;
    const float s1 = *s1p;

    for (; t < ntotal; t += G) {
        const bool has_next = (t + G) < ntotal;

        for (int kc = 0; kc < kch; kc++) {
            cp_wait<1>();
            __syncthreads();

            if (kc == kch - 2 && has_next) set_ptrs(t + G);
            const bool do_pre = (kc < kch - 2) || has_next;
            const int preK = (kc + 2 < kch) ? (kc + 2) : (kc + 2 - kch);
            const int pslot = (cslot + 2 >= 3) ? (cslot - 1) : (cslot + 2);

            const uint32_t st = sb + cslot * STAGE_BYTES;
#pragma unroll
            for (int ks = 0; ks < 4; ks++) {
                const uint32_t stk = st + kxo[ks];
                uint32_t fa[MI][4];
#pragma unroll
                for (int mi = 0; mi < MI; mi++)
                    ldsm_x4(fa[mi][0], fa[mi][1], fa[mi][2], fa[mi][3],
                            stk + baseA[mi]);
                uint32_t fb[NJ][4];
#pragma unroll
                for (int jj = 0; jj < NJ; jj++)
                    ldsm_x4(fb[jj][0], fb[jj][1], fb[jj][2], fb[jj][3],
                            stk + baseB[jj]);
                if (do_pre) load_part(preK, pslot, ks);
#pragma unroll
                for (int g = 0; g < NB; g++)
#pragma unroll
                    for (int mi = 0; mi < MI; mi++)
#pragma unroll
                        for (int ni = 0; ni < NMMA; ni++)
                            mma16816(acc[g][mi][ni], fa[mi],
                                     &fb[g * (NMMA / 2) + (ni >> 1)][(ni & 1) * 2]);
            }
            CP_COMMIT();
            cslot = (cslot + 1 == 3) ? 0 : cslot + 1;
        }

        int mt, nt;
        decode(t, mt, nt);
        if (NB == 2) {
            __half* out = (__half*)outp;
#pragma unroll
            for (int mi = 0; mi < MI; mi++)
#pragma unroll
                for (int ni = 0; ni < NMMA; ni++) {
                    int row0 = mt * BM + wm * 64 + mi * 16 + (lane >> 2);
                    int col  = nt * BN_EACH + wn * WN_COLS + ni * 8 + (lane & 3) * 2;
#pragma unroll
                    for (int h = 0; h < 2; h++) {
                        int row = row0 + h * 8;
                        float g0 = s0 * acc[0][mi][ni][2 * h + 0];
                        float g1 = s0 * acc[0][mi][ni][2 * h + 1];
                        float u0 = s1 * acc[1][mi][ni][2 * h + 0];
                        float u1 = s1 * acc[1][mi][ni][2 * h + 1];
                        float r0 = g0 / (1.f + __expf(-g0)) * u0;
                        float r1 = g1 / (1.f + __expf(-g1)) * u1;
                        *(__half2*)(out + (size_t)row * ncols + col) =
                            __floats2half2_rn(r0, r1);
                    }
                }
        } else {
            float* out = (float*)outp;
#pragma unroll
            for (int mi = 0; mi < MI; mi++)
#pragma unroll
                for (int ni = 0; ni < NMMA; ni++) {
                    int row0 = mt * BM + wm * 64 + mi * 16 + (lane >> 2);
                    int col  = nt * BN_EACH + wn * WN_COLS + ni * 8 + (lane & 3) * 2;
#pragma unroll
                    for (int h = 0; h < 2; h++) {
                        int row = row0 + h * 8;
                        float2 v;
                        v.x = s0 * acc[0][mi][ni][2 * h + 0];
                        v.y = s0 * acc[0][mi][ni][2 * h + 1];
                        *(float2*)(out + (size_t)row * ncols + col) = v;
                    }
                }
        }
#pragma unroll
        for (int g = 0; g < NB; g++)
#pragma unroll
            for (int mi = 0; mi < MI; mi++)
#pragma unroll
                for (int ni = 0; ni < NMMA; ni++)
#pragma unroll
                    for (int q = 0; q < 4; q++) acc[g][mi][ni][q] = 0.f;
    }
}

// ============================================================================
// Host side — fork-join stream overlap: cvt_wd runs concurrently with GEMM1.
//   main:  cvt_xw -> GEMM1 ----------------+-> GEMM2
//   fork:        \-> cvt_wd (event join) --/
// ============================================================================
extern "C" void kernel_launch(void* const* d_in, const int* in_sizes, int n_in,
                              void* d_out, int out_size) {
    const float* x  = (const float*)d_in[0];
    const int*   wg = (const int*)d_in[1];
    const int*   wu = (const int*)d_in[2];
    const int*   wd = (const int*)d_in[3];
    const float* sg = (const float*)d_in[4];
    const float* su = (const float*)d_in[5];
    const float* sd = (const float*)d_in[6];

    void *px, *pwg, *pwu, *pwd, *pmid;
    cudaGetSymbolAddress(&px,  g_x);
    cudaGetSymbolAddress(&pwg, g_wg);
    cudaGetSymbolAddress(&pwu, g_wu);
    cudaGetSymbolAddress(&pwd, g_wd);
    cudaGetSymbolAddress(&pmid, g_mid);

    int dev = 0, sms = 148;
    cudaGetDevice(&dev);
    cudaDeviceGetAttribute(&sms, cudaDevAttrMultiProcessorCount, dev);
    const int gpersist = 2 * sms;

    constexpr int SMEM_BYTES = 3 * 32768;   // 98304 per CTA -> 2 CTAs/SM
    cudaFuncSetAttribute(ffn_gemm<2, 64>,
                         cudaFuncAttributeMaxDynamicSharedMemorySize, SMEM_BYTES);
    cudaFuncSetAttribute(ffn_gemm<1, 128>,
                         cudaFuncAttributeMaxDynamicSharedMemorySize, SMEM_BYTES);

    // fork stream + events (host objects; created per call, O(1) calls total)
    cudaStream_t s1;
    cudaEvent_t eFork, eJoin;
    cudaStreamCreateWithFlags(&s1, cudaStreamNonBlocking);
    cudaEventCreateWithFlags(&eFork, cudaEventDisableTiming);
    cudaEventCreateWithFlags(&eJoin, cudaEventDisableTiming);

    // fork point on the main (captured) stream
    cudaEventRecord(eFork, 0);
    cudaStreamWaitEvent(s1, eFork, 0);

    // forked branch: down-proj weight convert (only GEMM2 needs it)
    cvt_wd<<<BW, 256, 0, s1>>>((const int4*)wd, (uint4*)pwd);
    cudaEventRecord(eJoin, s1);

    // main branch: x + gate/up converts, then GEMM1
    cvt_xw<<<BX + 2 * BW, 256>>>(
        (const float4*)x, (const int4*)wg, (const int4*)wu,
        (uint4*)px, (uint4*)pwg, (uint4*)pwu);

    {
        int mtiles = MROWS / 128;   // 64
        int ntiles = HID / 64;      // 172
        int ntotal = mtiles * ntiles;
        int grid = gpersist < ntotal ? gpersist : ntotal;
        ffn_gemm<2, 64><<<grid, 256, SMEM_BYTES>>>(
            (const __half*)px, (const __half*)pwg, (const __half*)pwu,
            pmid, sg, su, DIMN, ntiles, ntotal, HID);
    }

    // join: GEMM2 needs both g_mid (main) and pwd (forked)
    cudaStreamWaitEvent(0, eJoin, 0);

    {
        int mtiles = MROWS / 128;   // 64
        int ntiles = DIMN / 128;    // 32
        int ntotal = mtiles * ntiles;
        int grid = gpersist < ntotal ? gpersist : ntotal;
        ffn_gemm<1, 128><<<grid, 256, SMEM_BYTES>>>(
            (const __half*)pmid, (const __half*)pwd, (const __half*)pwd,
            d_out, sd, sd, HID, ntiles, ntotal, DIMN);
    }
}